// round 9
// baseline (speedup 1.0000x reference)
#include <cuda_runtime.h>
#include <cuda_bf16.h>
#include <cstdint>

#define NROWS 1024
#define DIM   256
#define HID   512
#define GRID  256
#define RS2   40               // smem row stride (bf16): 80B, conflict-free LDSM
#define ASZ   (64 * RS2 * 2)   // 5120 B per 64x32 bf16 tile
#define BUFSZ (4 * ASZ)        // Ah, Al, Bh, Bl

// ============================ device scratch =================================
__device__ __align__(16) __nv_bfloat16 g_Xh[2][NROWS * DIM];     // H, P (hi)
__device__ __align__(16) __nv_bfloat16 g_Xl[2][NROWS * DIM];     // H, P (lo)
__device__ __align__(16) __nv_bfloat16 g_W1t_h [HID * DIM],      g_W1t_l [HID * DIM];      // [512n][256k]
__device__ __align__(16) __nv_bfloat16 g_W1gt_h[HID * 2 * DIM],  g_W1gt_l[HID * 2 * DIM];  // [512n][512k]
__device__ __align__(16) __nv_bfloat16 g_W2t_h [DIM * HID],      g_W2t_l [DIM * HID];      // [256n][512k]
__device__ __align__(16) __nv_bfloat16 g_W2gt_h[DIM * HID],      g_W2gt_l[DIM * HID];
__device__ __align__(16) __nv_bfloat16 g_A1h[2][NROWS * HID],    g_A1l[2][NROWS * HID];
__device__ __align__(16) float  g_ypart[2 * 32 * DIM];
__device__ double   g_acc;
__device__ unsigned g_bar;          // monotonic barrier counter (never reset)

// ============================ helpers ========================================
__device__ __forceinline__ uint32_t smem_u32(const void* p) {
    uint32_t a;
    asm("{ .reg .u64 t; cvta.to.shared.u64 t, %1; cvt.u32.u64 %0, t; }" : "=r"(a) : "l"(p));
    return a;
}
__device__ __forceinline__ void cvt2(float v0, float v1, uint32_t& hp, uint32_t& lp) {
    __nv_bfloat16 h0 = __float2bfloat16(v0);
    __nv_bfloat16 h1 = __float2bfloat16(v1);
    __nv_bfloat16 l0 = __float2bfloat16(v0 - __bfloat162float(h0));
    __nv_bfloat16 l1 = __float2bfloat16(v1 - __bfloat162float(h1));
    hp = ((uint32_t)__bfloat16_as_ushort(h1) << 16) | __bfloat16_as_ushort(h0);
    lp = ((uint32_t)__bfloat16_as_ushort(l1) << 16) | __bfloat16_as_ushort(l0);
}
__device__ __forceinline__ void mma16816(float* c, const uint32_t* a,
                                         const uint32_t b0, const uint32_t b1) {
    asm volatile(
        "mma.sync.aligned.m16n8k16.row.col.f32.bf16.bf16.f32 "
        "{%0,%1,%2,%3}, {%4,%5,%6,%7}, {%8,%9}, {%0,%1,%2,%3};"
        : "+f"(c[0]), "+f"(c[1]), "+f"(c[2]), "+f"(c[3])
        : "r"(a[0]), "r"(a[1]), "r"(a[2]), "r"(a[3]), "r"(b0), "r"(b1));
}
#define LDSM4(r0, r1, r2, r3, addr)                                              \
    asm volatile("ldmatrix.sync.aligned.m8n8.x4.shared.b16 {%0,%1,%2,%3}, [%4];" \
        : "=r"(r0), "=r"(r1), "=r"(r2), "=r"(r3) : "r"(addr))
#define CP16(dst, src) \
    asm volatile("cp.async.cg.shared.global [%0], [%1], 16;" :: "r"(dst), "l"(src))
#define CP_COMMIT() asm volatile("cp.async.commit_group;" ::: "memory")
#define CP_WAIT1()  asm volatile("cp.async.wait_group 1;" ::: "memory")
#define CP_WAIT0()  asm volatile("cp.async.wait_group 0;" ::: "memory")

// Grid-wide barrier: monotonic ticket, round inferred from ticket/GRID.
// Safe because all GRID CTAs are co-resident (128 thr, 41KB smem -> 2 CTAs/SM).
__device__ __forceinline__ void grid_barrier() {
    __syncthreads();
    if (threadIdx.x == 0) {
        __threadfence();                               // release phase writes
        unsigned tk = atomicAdd(&g_bar, 1u);
        unsigned target = (tk / GRID + 1u) * GRID;
        while ((int)(*(volatile unsigned*)&g_bar - target) < 0) { }
        __threadfence();                               // acquire
    }
    __syncthreads();
}

// ============================================================================
// GEMM building blocks (64x64 CTA tile, BK=32, 4 warps 2x2, bf16 3-prod split)
// ============================================================================
__device__ __forceinline__ void load_async32(uint32_t dst,
    const __nv_bfloat16* __restrict__ Ah, const __nv_bfloat16* __restrict__ Al,
    int m0, int lda, int ka,
    const __nv_bfloat16* __restrict__ Bh, const __nv_bfloat16* __restrict__ Bl,
    int n0, int ldb, int kb, int tid)
{
    #pragma unroll
    for (int i = 0; i < 2; ++i) {
        int idx = tid + i * 128;           // 256 granules per tile
        int row = idx >> 2, w = idx & 3;
        uint32_t doff = (uint32_t)row * (RS2 * 2) + w * 16;
        size_t sa = (size_t)(m0 + row) * lda + ka + w * 8;
        size_t sb = (size_t)(n0 + row) * ldb + kb + w * 8;
        CP16(dst + 0 * ASZ + doff, Ah + sa);
        CP16(dst + 1 * ASZ + doff, Al + sa);
        CP16(dst + 2 * ASZ + doff, Bh + sb);
        CP16(dst + 3 * ASZ + doff, Bl + sb);
    }
}

__device__ __forceinline__ void consume32(uint32_t b, float acc[2][4][4],
                                          int wm, int wn, int lane)
{
    const int arow  = lane & 15;
    const int akoff = (lane >> 4) * 8;
    const int g     = lane >> 3;
    const int brow  = ((g >> 1) & 1) * 8 + (lane & 7);
    const int bkoff = (g & 1) * 8;
    #pragma unroll
    for (int ks = 0; ks < 2; ++ks) {
        const int kb = ks * 16;
        uint32_t ah[2][4], al[2][4];
        #pragma unroll
        for (int mi = 0; mi < 2; ++mi) {
            uint32_t ro = (uint32_t)(wm * 32 + mi * 16 + arow) * (RS2 * 2) + (kb + akoff) * 2;
            LDSM4(ah[mi][0], ah[mi][1], ah[mi][2], ah[mi][3], b + 0 * ASZ + ro);
            LDSM4(al[mi][0], al[mi][1], al[mi][2], al[mi][3], b + 1 * ASZ + ro);
        }
        uint32_t bh[2][4], bl[2][4];
        #pragma unroll
        for (int njp = 0; njp < 2; ++njp) {
            uint32_t ro = (uint32_t)(wn * 32 + njp * 16 + brow) * (RS2 * 2) + (kb + bkoff) * 2;
            LDSM4(bh[njp][0], bh[njp][1], bh[njp][2], bh[njp][3], b + 2 * ASZ + ro);
            LDSM4(bl[njp][0], bl[njp][1], bl[njp][2], bl[njp][3], b + 3 * ASZ + ro);
        }
        #pragma unroll
        for (int mi = 0; mi < 2; ++mi)
            #pragma unroll
            for (int njp = 0; njp < 2; ++njp) {
                mma16816(acc[mi][2*njp],     ah[mi], bh[njp][0], bh[njp][1]);
                mma16816(acc[mi][2*njp],     ah[mi], bl[njp][0], bl[njp][1]);
                mma16816(acc[mi][2*njp],     al[mi], bh[njp][0], bh[njp][1]);
                mma16816(acc[mi][2*njp + 1], ah[mi], bh[njp][2], bh[njp][3]);
                mma16816(acc[mi][2*njp + 1], ah[mi], bl[njp][2], bl[njp][3]);
                mma16816(acc[mi][2*njp + 1], al[mi], bh[njp][2], bh[njp][3]);
            }
    }
}

// ============================================================================
// The persistent kernel: prep | barrier | layer-1 | barrier | layer-2 | barrier
// ============================================================================
union SmemU {
    char  bufs[2 * BUFSZ];     // 40960 B: GEMM double buffers
    float wtile[32][33];       // prep transpose tile (4224 B)
};

__global__ void __launch_bounds__(128, 2)
kFused(const float* __restrict__ H,   const float* __restrict__ P,
       const float* __restrict__ G,
       const float* __restrict__ W1,  const float* __restrict__ b1,
       const float* __restrict__ W2,  const float* __restrict__ b2,
       const float* __restrict__ W1g, const float* __restrict__ b1g,
       const float* __restrict__ W2g, const float* __restrict__ b2g,
       float* __restrict__ out)
{
    __shared__ SmemU u;
    __shared__ float  ym_s[64];
    __shared__ double red[4];

    const int bid  = blockIdx.x;
    const int tid  = threadIdx.x;
    const int lane = tid & 31, wrp = tid >> 5;
    const int wm   = wrp >> 1, wn = wrp & 1;
    const uint32_t sb = smem_u32(u.bufs);

    // ======================= Phase 0: prep ==================================
    if (bid == 0 && tid == 0) g_acc = 0.0;

    // ---- column-mean partials (CTAs 0..63) ----
    if (bid < 64) {
        const int which = bid >> 5, part = bid & 31;
        const float* Y = which ? G : P;
        const int r0 = part * 32;
        #pragma unroll
        for (int h = 0; h < 2; ++h) {
            int d = tid + h * 128;
            float s = 0.f;
            #pragma unroll 8
            for (int r = 0; r < 32; ++r) s += Y[(r0 + r) * DIM + d];
            g_ypart[(which * 32 + part) * DIM + d] = s;
        }
    }

    // ---- X split: 131072 float4 total, 512 per CTA ----
    #pragma unroll
    for (int i = 0; i < 4; ++i) {
        int idx = bid * 512 + i * 128 + tid;
        int which = idx >> 16;
        int base  = (idx & 65535) * 4;
        const float* X = which ? P : H;
        float4 v = *reinterpret_cast<const float4*>(&X[base]);
        uint32_t h0, l0, h1, l1;
        cvt2(v.x, v.y, h0, l0);
        cvt2(v.z, v.w, h1, l1);
        *reinterpret_cast<uint2*>(&g_Xh[which][base]) = make_uint2(h0, h1);
        *reinterpret_cast<uint2*>(&g_Xl[which][base]) = make_uint2(l0, l1);
    }

    // ---- weight transpose+split: 640 32x32 tiles ----
    for (int uu = bid; uu < 640; uu += GRID) {
        int t = uu;
        const float* src; __nv_bfloat16 *dh, *dl; int K, N, kt, nt;
        if (t < 128)      { src = W1;  dh = g_W1t_h;  dl = g_W1t_l;  K = 256; N = 512; kt = t >> 4; nt = t & 15; }
        else if (t < 384) { t -= 128; src = W1g; dh = g_W1gt_h; dl = g_W1gt_l; K = 512; N = 512; kt = t >> 4; nt = t & 15; }
        else if (t < 512) { t -= 384; src = W2;  dh = g_W2t_h;  dl = g_W2t_l;  K = 512; N = 256; kt = t >> 3; nt = t & 7; }
        else              { t -= 512; src = W2g; dh = g_W2gt_h; dl = g_W2gt_l; K = 512; N = 256; kt = t >> 3; nt = t & 7; }
        const int k0 = kt * 32, n0 = nt * 32;

        __syncthreads();                    // tile reuse guard
        #pragma unroll
        for (int i = 0; i < 2; ++i) {
            int ii = tid + i * 128;
            int r = ii >> 3, c4 = ii & 7;
            float4 v = *reinterpret_cast<const float4*>(&src[(k0 + r) * N + n0 + c4 * 4]);
            u.wtile[r][c4*4+0] = v.x; u.wtile[r][c4*4+1] = v.y;
            u.wtile[r][c4*4+2] = v.z; u.wtile[r][c4*4+3] = v.w;
        }
        __syncthreads();
        #pragma unroll
        for (int i = 0; i < 2; ++i) {
            int ii = tid + i * 128;
            int nr = ii >> 3, kc = (ii & 7) * 4;
            uint32_t h0, l0, h1, l1;
            cvt2(u.wtile[kc+0][nr], u.wtile[kc+1][nr], h0, l0);
            cvt2(u.wtile[kc+2][nr], u.wtile[kc+3][nr], h1, l1);
            size_t o = (size_t)(n0 + nr) * K + k0 + kc;
            *reinterpret_cast<uint2*>(&dh[o]) = make_uint2(h0, h1);
            *reinterpret_cast<uint2*>(&dl[o]) = make_uint2(l0, l1);
        }
    }

    grid_barrier();

    // ======================= Phase 1: layer-1 GEMM ==========================
    {
        const int prob = bid >> 7, t = bid & 127;
        const int m0   = (t >> 3) * 64, n0 = (t & 7) * 64;
        const __nv_bfloat16* Wh = prob ? g_W1gt_h : g_W1t_h;
        const __nv_bfloat16* Wl = prob ? g_W1gt_l : g_W1t_l;
        const int K = prob ? 2 * DIM : DIM;
        const int nch = K / 32;

        float acc[2][4][4] = {};
        load_async32(sb, g_Xh[0], g_Xl[0], m0, DIM, 0, Wh, Wl, n0, K, 0, tid);
        CP_COMMIT();
        for (int ch = 0; ch < nch; ++ch) {
            if (ch + 1 < nch) {
                int k0 = (ch + 1) * 32;
                int xi = (prob && k0 >= DIM) ? 1 : 0;    // concat: H then P
                load_async32(sb + ((ch + 1) & 1) * BUFSZ,
                             g_Xh[xi], g_Xl[xi], m0, DIM, k0 & (DIM - 1),
                             Wh, Wl, n0, K, k0, tid);
                CP_COMMIT();
                CP_WAIT1();
            } else {
                CP_WAIT0();
            }
            __syncthreads();
            consume32(sb + (ch & 1) * BUFSZ, acc, wm, wn, lane);
            __syncthreads();
        }

        const float* Bias = prob ? b1g : b1;
        __nv_bfloat16* Oh = g_A1h[prob];
        __nv_bfloat16* Ol = g_A1l[prob];
        const int qr = lane >> 2, qc = (lane & 3) * 2;
        #pragma unroll
        for (int mi = 0; mi < 2; ++mi) {
            #pragma unroll
            for (int nj = 0; nj < 4; ++nj) {
                int row = m0 + wm * 32 + mi * 16 + qr;
                int col = n0 + wn * 32 + nj * 8 + qc;
                float bz0 = Bias[col], bz1 = Bias[col + 1];
                uint32_t hp, lp;
                cvt2(fmaxf(acc[mi][nj][0] + bz0, 0.f), fmaxf(acc[mi][nj][1] + bz1, 0.f), hp, lp);
                *reinterpret_cast<uint32_t*>(&Oh[(size_t)row * HID + col]) = hp;
                *reinterpret_cast<uint32_t*>(&Ol[(size_t)row * HID + col]) = lp;
                cvt2(fmaxf(acc[mi][nj][2] + bz0, 0.f), fmaxf(acc[mi][nj][3] + bz1, 0.f), hp, lp);
                *reinterpret_cast<uint32_t*>(&Oh[(size_t)(row + 8) * HID + col]) = hp;
                *reinterpret_cast<uint32_t*>(&Ol[(size_t)(row + 8) * HID + col]) = lp;
            }
        }
    }

    grid_barrier();

    // ======================= Phase 2: layer-2 + CLUB ========================
    {
        const int prob  = bid >> 7, t = bid & 127;
        const int m0    = (t >> 3) * 64;
        const int n0    = ((t >> 1) & 3) * 64;
        const int chunk = t & 1;
        const int kbeg  = chunk * 256;

        if (tid < 64) {                    // ym for this n-tile
            float sm = 0.f;
            #pragma unroll 8
            for (int b = 0; b < 32; ++b) sm += g_ypart[(prob * 32 + b) * DIM + n0 + tid];
            ym_s[tid] = sm * (1.0f / NROWS);
        }

        const __nv_bfloat16* Ah = g_A1h[prob];
        const __nv_bfloat16* Al = g_A1l[prob];
        const __nv_bfloat16* Wh = prob ? g_W2gt_h : g_W2t_h;
        const __nv_bfloat16* Wl = prob ? g_W2gt_l : g_W2t_l;

        float acc[2][4][4] = {};
        load_async32(sb, Ah, Al, m0, HID, kbeg, Wh, Wl, n0, HID, kbeg, tid);
        CP_COMMIT();
        for (int ch = 0; ch < 8; ++ch) {
            if (ch < 7) {
                int k0 = kbeg + (ch + 1) * 32;
                load_async32(sb + ((ch + 1) & 1) * BUFSZ,
                             Ah, Al, m0, HID, k0, Wh, Wl, n0, HID, k0, tid);
                CP_COMMIT();
                CP_WAIT1();
            } else {
                CP_WAIT0();
            }
            __syncthreads();
            consume32(sb + (ch & 1) * BUFSZ, acc, wm, wn, lane);
            __syncthreads();
        }

        const float* Bias = prob ? b2g : b2;
        const float* Y    = prob ? G   : P;
        const bool  wb    = (chunk == 0);  // bias rides on chunk 0 (linearity)
        const int qr = lane >> 2, qc = (lane & 3) * 2;
        float local = 0.f;
        #pragma unroll
        for (int mi = 0; mi < 2; ++mi) {
            #pragma unroll
            for (int nj = 0; nj < 4; ++nj) {
                int row = m0 + wm * 32 + mi * 16 + qr;
                int col = n0 + wn * 32 + nj * 8 + qc;
                float bz0 = wb ? Bias[col]     : 0.f;
                float bz1 = wb ? Bias[col + 1] : 0.f;
                float ym0 = ym_s[col - n0], ym1 = ym_s[col - n0 + 1];
                float2 y0 = *reinterpret_cast<const float2*>(&Y[(size_t)row * DIM + col]);
                float2 y1 = *reinterpret_cast<const float2*>(&Y[(size_t)(row + 8) * DIM + col]);
                local += (acc[mi][nj][0] + bz0) * (y0.x - ym0)
                       + (acc[mi][nj][1] + bz1) * (y0.y - ym1)
                       + (acc[mi][nj][2] + bz0) * (y1.x - ym0)
                       + (acc[mi][nj][3] + bz1) * (y1.y - ym1);
            }
        }
        #pragma unroll
        for (int off = 16; off > 0; off >>= 1)
            local += __shfl_xor_sync(0xFFFFFFFF, local, off);
        if (lane == 0) red[wrp] = (double)local;
        __syncthreads();
        if (tid == 0)
            atomicAdd(&g_acc, (red[0] + red[1]) + (red[2] + red[3]));
    }

    grid_barrier();

    // ======================= Phase 3: scalar out ============================
    if (bid == 0 && tid == 0) {
        double total = *(volatile double*)&g_acc;
        out[0] = (float)(total * (1.0 / NROWS));
    }
}

// ----------------------------------------------------------------------------
extern "C" void kernel_launch(void* const* d_in, const int* in_sizes, int n_in,
                              void* d_out, int out_size)
{
    const float* H   = (const float*)d_in[0];
    const float* P   = (const float*)d_in[1];
    const float* G   = (const float*)d_in[2];
    const float* W1  = (const float*)d_in[3];
    const float* b1  = (const float*)d_in[4];
    const float* W2  = (const float*)d_in[5];
    const float* b2  = (const float*)d_in[6];
    const float* W1g = (const float*)d_in[7];
    const float* b1g = (const float*)d_in[8];
    const float* W2g = (const float*)d_in[9];
    const float* b2g = (const float*)d_in[10];
    float* out = (float*)d_out;

    kFused<<<GRID, 128>>>(H, P, G, W1, b1, W2, b2, W1g, b1g, W2g, b2g, out);
}

// round 10
// speedup vs baseline: 1.1160x; 1.1160x over previous
#include <cuda_runtime.h>
#include <cuda_bf16.h>
#include <cstdint>

#define NROWS 1024
#define DIM   256
#define HID   512
#define RS2   40               // A smem row stride (bf16): 80B, conflict-free
#define RSB   72               // B smem row stride (bf16): 144B, conflict-free trans-LDSM
#define ASZ   (64 * RS2 * 2)   // 5120 B : 64m x 32k bf16 tile
#define BSZ   (32 * RSB * 2)   // 4608 B : 32k x 64n bf16 tile
#define OFF_AH 0
#define OFF_AL ASZ
#define OFF_BH (2 * ASZ)
#define OFF_BL (2 * ASZ + BSZ)
#define BUFSZ  (2 * ASZ + 2 * BSZ)   // 19456 B

// ============================ device scratch =================================
__device__ __align__(16) __nv_bfloat16 g_Xh[2][NROWS * DIM];    // H, P (hi)
__device__ __align__(16) __nv_bfloat16 g_Xl[2][NROWS * DIM];    // H, P (lo)
// weights split elementwise, NATURAL [k][n] layout (n contiguous)
__device__ __align__(16) __nv_bfloat16 g_W1h [DIM * HID],      g_W1l [DIM * HID];
__device__ __align__(16) __nv_bfloat16 g_W1gh[2 * DIM * HID],  g_W1gl[2 * DIM * HID];
__device__ __align__(16) __nv_bfloat16 g_W2h [HID * DIM],      g_W2l [HID * DIM];
__device__ __align__(16) __nv_bfloat16 g_W2gh[HID * DIM],      g_W2gl[HID * DIM];
__device__ __align__(16) __nv_bfloat16 g_A1h[2][NROWS * HID],  g_A1l[2][NROWS * HID];
__device__ __align__(16) float  g_ypart[2 * 32 * DIM];
__device__ double   g_acc;
__device__ unsigned g_ticket;

// ============================ helpers ========================================
__device__ __forceinline__ uint32_t smem_u32(const void* p) {
    uint32_t a;
    asm("{ .reg .u64 t; cvta.to.shared.u64 t, %1; cvt.u32.u64 %0, t; }" : "=r"(a) : "l"(p));
    return a;
}
__device__ __forceinline__ void cvt2(float v0, float v1, uint32_t& hp, uint32_t& lp) {
    __nv_bfloat16 h0 = __float2bfloat16(v0);
    __nv_bfloat16 h1 = __float2bfloat16(v1);
    __nv_bfloat16 l0 = __float2bfloat16(v0 - __bfloat162float(h0));
    __nv_bfloat16 l1 = __float2bfloat16(v1 - __bfloat162float(h1));
    hp = ((uint32_t)__bfloat16_as_ushort(h1) << 16) | __bfloat16_as_ushort(h0);
    lp = ((uint32_t)__bfloat16_as_ushort(l1) << 16) | __bfloat16_as_ushort(l0);
}
__device__ __forceinline__ void mma16816(float* c, const uint32_t* a,
                                         const uint32_t b0, const uint32_t b1) {
    asm volatile(
        "mma.sync.aligned.m16n8k16.row.col.f32.bf16.bf16.f32 "
        "{%0,%1,%2,%3}, {%4,%5,%6,%7}, {%8,%9}, {%0,%1,%2,%3};"
        : "+f"(c[0]), "+f"(c[1]), "+f"(c[2]), "+f"(c[3])
        : "r"(a[0]), "r"(a[1]), "r"(a[2]), "r"(a[3]), "r"(b0), "r"(b1));
}
#define LDSM4(r0, r1, r2, r3, addr)                                              \
    asm volatile("ldmatrix.sync.aligned.m8n8.x4.shared.b16 {%0,%1,%2,%3}, [%4];" \
        : "=r"(r0), "=r"(r1), "=r"(r2), "=r"(r3) : "r"(addr))
#define LDSM4T(r0, r1, r2, r3, addr)                                                   \
    asm volatile("ldmatrix.sync.aligned.m8n8.x4.trans.shared.b16 {%0,%1,%2,%3}, [%4];" \
        : "=r"(r0), "=r"(r1), "=r"(r2), "=r"(r3) : "r"(addr))
#define CP16(dst, src) \
    asm volatile("cp.async.cg.shared.global [%0], [%1], 16;" :: "r"(dst), "l"(src))
#define CP_COMMIT() asm volatile("cp.async.commit_group;" ::: "memory")
#define CP_WAIT1()  asm volatile("cp.async.wait_group 1;" ::: "memory")
#define CP_WAIT0()  asm volatile("cp.async.wait_group 0;" ::: "memory")

// ============================================================================
// kPrep: pure streaming splits (no transpose, no smem) + means partials.
// blocks 0..255: X split | 256..575: W split | 576..639: means. block = 256.
// Each split thread: 8 consecutive floats -> one 16B hi store + one 16B lo store.
// ============================================================================
__global__ void __launch_bounds__(256) kPrep(const float* __restrict__ H,
                                             const float* __restrict__ P,
                                             const float* __restrict__ G,
                                             const float* __restrict__ W1,
                                             const float* __restrict__ W1g,
                                             const float* __restrict__ W2,
                                             const float* __restrict__ W2g)
{
    const int bid = blockIdx.x, tid = threadIdx.x;
    if (bid == 0 && tid == 0) { g_acc = 0.0; g_ticket = 0u; }

    if (bid < 576) {
        const float* src;
        __nv_bfloat16 *dh, *dl;
        int unit;                                    // unit = 8 floats
        if (bid < 256) {                             // X: 2 x 262144 floats
            int u = bid * 256 + tid;                 // 0..65535
            int which = u >> 15;                     // 32768 units per tensor
            unit = u & 32767;
            src = which ? P : H;
            dh = g_Xh[which]; dl = g_Xl[which];
        } else {                                     // W: 81920 units total
            int u = (bid - 256) * 256 + tid;         // 0..81919
            if (u < 16384)      { src = W1;  dh = g_W1h;  dl = g_W1l;  unit = u; }
            else if (u < 49152) { src = W1g; dh = g_W1gh; dl = g_W1gl; unit = u - 16384; }
            else if (u < 65536) { src = W2;  dh = g_W2h;  dl = g_W2l;  unit = u - 49152; }
            else                { src = W2g; dh = g_W2gh; dl = g_W2gl; unit = u - 65536; }
        }
        const int base = unit * 8;
        float4 v0 = *reinterpret_cast<const float4*>(&src[base]);
        float4 v1 = *reinterpret_cast<const float4*>(&src[base + 4]);
        uint4 hq, lq;
        cvt2(v0.x, v0.y, hq.x, lq.x);
        cvt2(v0.z, v0.w, hq.y, lq.y);
        cvt2(v1.x, v1.y, hq.z, lq.z);
        cvt2(v1.z, v1.w, hq.w, lq.w);
        *reinterpret_cast<uint4*>(&dh[base]) = hq;
        *reinterpret_cast<uint4*>(&dl[base]) = lq;
        return;
    }

    {                                                // ---- means partials ----
        const int t = bid - 576;
        const int which = t >> 5, part = t & 31;
        const float* Y = which ? G : P;
        const int r0 = part * 32;
        float s = 0.f;
        #pragma unroll 8
        for (int r = 0; r < 32; ++r) s += Y[(r0 + r) * DIM + tid];
        g_ypart[(which * 32 + part) * DIM + tid] = s;
    }
}

// ============================================================================
// cp.async chunk loader.
// A: 64m x 32k from [m][k] arrays (lda) ; B: 32k x 64n from [k][n] arrays (ldb)
// ============================================================================
__device__ __forceinline__ void load_async32(uint32_t dst,
    const __nv_bfloat16* __restrict__ Ah, const __nv_bfloat16* __restrict__ Al,
    int m0, int lda, int ka,
    const __nv_bfloat16* __restrict__ Bh, const __nv_bfloat16* __restrict__ Bl,
    int n0, int ldb, int kb, int tid)
{
    #pragma unroll
    for (int i = 0; i < 2; ++i) {
        int idx = tid + i * 128;
        {   // A: 256 granules (64 rows x 4)
            int row = idx >> 2, w = idx & 3;
            uint32_t doff = (uint32_t)row * (RS2 * 2) + w * 16;
            size_t sa = (size_t)(m0 + row) * lda + ka + w * 8;
            CP16(dst + OFF_AH + doff, Ah + sa);
            CP16(dst + OFF_AL + doff, Al + sa);
        }
        {   // B: 256 granules (32 k-rows x 8)
            int row = idx >> 3, w = idx & 7;
            uint32_t doff = (uint32_t)row * (RSB * 2) + w * 16;
            size_t sb = (size_t)(kb + row) * ldb + n0 + w * 8;
            CP16(dst + OFF_BH + doff, Bh + sb);
            CP16(dst + OFF_BL + doff, Bl + sb);
        }
    }
}

// ============================================================================
// consume one 64x64x32 chunk: ldmatrix (A) + ldmatrix.trans (B), 3-product HMMA.
// ============================================================================
__device__ __forceinline__ void consume32(uint32_t b, float acc[2][4][4],
                                          int wm, int wn, int lane)
{
    const int arow  = lane & 15;
    const int akoff = (lane >> 4) * 8;
    const int g     = lane >> 3;                 // 0..3
    const int bkrow = (g & 1) * 8 + (lane & 7);  // k-row within k16
    const int bnoff = (g >> 1) * 8;              // n-block 0/8
    #pragma unroll
    for (int ks = 0; ks < 2; ++ks) {
        const int kb = ks * 16;
        uint32_t ah[2][4], al[2][4];
        #pragma unroll
        for (int mi = 0; mi < 2; ++mi) {
            uint32_t ro = (uint32_t)(wm * 32 + mi * 16 + arow) * (RS2 * 2) + (kb + akoff) * 2;
            LDSM4(ah[mi][0], ah[mi][1], ah[mi][2], ah[mi][3], b + OFF_AH + ro);
            LDSM4(al[mi][0], al[mi][1], al[mi][2], al[mi][3], b + OFF_AL + ro);
        }
        uint32_t bh[2][4], bl[2][4];   // [njp][r]: (r0,r1)=b0,b1 of nj even; (r2,r3)=nj odd
        #pragma unroll
        for (int njp = 0; njp < 2; ++njp) {
            uint32_t ro = (uint32_t)(kb + bkrow) * (RSB * 2)
                        + (wn * 32 + njp * 16 + bnoff) * 2;
            LDSM4T(bh[njp][0], bh[njp][1], bh[njp][2], bh[njp][3], b + OFF_BH + ro);
            LDSM4T(bl[njp][0], bl[njp][1], bl[njp][2], bl[njp][3], b + OFF_BL + ro);
        }
        #pragma unroll
        for (int mi = 0; mi < 2; ++mi)
            #pragma unroll
            for (int njp = 0; njp < 2; ++njp) {
                mma16816(acc[mi][2*njp],     ah[mi], bh[njp][0], bh[njp][1]);
                mma16816(acc[mi][2*njp],     ah[mi], bl[njp][0], bl[njp][1]);
                mma16816(acc[mi][2*njp],     al[mi], bh[njp][0], bh[njp][1]);
                mma16816(acc[mi][2*njp + 1], ah[mi], bh[njp][2], bh[njp][3]);
                mma16816(acc[mi][2*njp + 1], ah[mi], bl[njp][2], bl[njp][3]);
                mma16816(acc[mi][2*njp + 1], al[mi], bh[njp][2], bh[njp][3]);
            }
    }
}

// ============================================================================
// kGemm1: layer-1 (relu, re-split hi/lo). 256 CTAs: prob(2) x m(16) x n(8).
// ============================================================================
__global__ void __launch_bounds__(128) kGemm1(const float* __restrict__ b1,
                                              const float* __restrict__ b1g)
{
    __shared__ __align__(16) char bufs[2 * BUFSZ];
    const uint32_t sb = smem_u32(bufs);
    const int tid  = threadIdx.x;
    const int lane = tid & 31, wrp = tid >> 5;
    const int wm   = wrp >> 1, wn = wrp & 1;
    const int bid  = blockIdx.x;
    const int prob = bid >> 7, t = bid & 127;
    const int m0   = (t >> 3) * 64, n0 = (t & 7) * 64;

    const __nv_bfloat16* Wh = prob ? g_W1gh : g_W1h;
    const __nv_bfloat16* Wl = prob ? g_W1gl : g_W1l;
    const int K = prob ? 2 * DIM : DIM;
    const int nch = K / 32;

    float acc[2][4][4] = {};
    load_async32(sb, g_Xh[0], g_Xl[0], m0, DIM, 0, Wh, Wl, n0, HID, 0, tid);
    CP_COMMIT();
    for (int ch = 0; ch < nch; ++ch) {
        if (ch + 1 < nch) {
            int k0 = (ch + 1) * 32;
            int xi = (prob && k0 >= DIM) ? 1 : 0;    // concat: H then P
            load_async32(sb + ((ch + 1) & 1) * BUFSZ,
                         g_Xh[xi], g_Xl[xi], m0, DIM, k0 & (DIM - 1),
                         Wh, Wl, n0, HID, k0, tid);
            CP_COMMIT();
            CP_WAIT1();
        } else {
            CP_WAIT0();
        }
        __syncthreads();
        consume32(sb + (ch & 1) * BUFSZ, acc, wm, wn, lane);
        __syncthreads();
    }

    const float* Bias = prob ? b1g : b1;
    __nv_bfloat16* Oh = g_A1h[prob];
    __nv_bfloat16* Ol = g_A1l[prob];
    const int qr = lane >> 2, qc = (lane & 3) * 2;
    #pragma unroll
    for (int mi = 0; mi < 2; ++mi) {
        #pragma unroll
        for (int nj = 0; nj < 4; ++nj) {
            int row = m0 + wm * 32 + mi * 16 + qr;
            int col = n0 + wn * 32 + nj * 8 + qc;
            float bz0 = Bias[col], bz1 = Bias[col + 1];
            uint32_t hp, lp;
            cvt2(fmaxf(acc[mi][nj][0] + bz0, 0.f), fmaxf(acc[mi][nj][1] + bz1, 0.f), hp, lp);
            *reinterpret_cast<uint32_t*>(&Oh[(size_t)row * HID + col]) = hp;
            *reinterpret_cast<uint32_t*>(&Ol[(size_t)row * HID + col]) = lp;
            cvt2(fmaxf(acc[mi][nj][2] + bz0, 0.f), fmaxf(acc[mi][nj][3] + bz1, 0.f), hp, lp);
            *reinterpret_cast<uint32_t*>(&Oh[(size_t)(row + 8) * HID + col]) = hp;
            *reinterpret_cast<uint32_t*>(&Ol[(size_t)(row + 8) * HID + col]) = lp;
        }
    }
}

// ============================================================================
// kGemm2: layer-2, split-K x2, fused CLUB epilogue, ticket-fused finish.
// 256 CTAs: prob(2) x m(16) x n(4) x chunk(2).
// ============================================================================
__global__ void __launch_bounds__(128) kGemm2(const float* __restrict__ b2,
                                              const float* __restrict__ b2g,
                                              const float* __restrict__ P,
                                              const float* __restrict__ G,
                                              float* __restrict__ out)
{
    __shared__ __align__(16) char bufs[2 * BUFSZ];
    __shared__ float  ym_s[64];
    __shared__ double red[4];
    const uint32_t sb = smem_u32(bufs);
    const int tid  = threadIdx.x;
    const int lane = tid & 31, wrp = tid >> 5;
    const int wm   = wrp >> 1, wn = wrp & 1;
    const int bid  = blockIdx.x;
    const int prob  = bid >> 7, t = bid & 127;
    const int m0    = (t >> 3) * 64;
    const int n0    = ((t >> 1) & 3) * 64;
    const int chunk = t & 1;
    const int kbeg  = chunk * 256;

    if (tid < 64) {                        // ym for this n-tile
        float sm = 0.f;
        #pragma unroll 8
        for (int b = 0; b < 32; ++b) sm += g_ypart[(prob * 32 + b) * DIM + n0 + tid];
        ym_s[tid] = sm * (1.0f / NROWS);
    }

    const __nv_bfloat16* Ah = g_A1h[prob];
    const __nv_bfloat16* Al = g_A1l[prob];
    const __nv_bfloat16* Wh = prob ? g_W2gh : g_W2h;
    const __nv_bfloat16* Wl = prob ? g_W2gl : g_W2l;

    float acc[2][4][4] = {};
    load_async32(sb, Ah, Al, m0, HID, kbeg, Wh, Wl, n0, DIM, kbeg, tid);
    CP_COMMIT();
    for (int ch = 0; ch < 8; ++ch) {
        if (ch < 7) {
            int k0 = kbeg + (ch + 1) * 32;
            load_async32(sb + ((ch + 1) & 1) * BUFSZ,
                         Ah, Al, m0, HID, k0, Wh, Wl, n0, DIM, k0, tid);
            CP_COMMIT();
            CP_WAIT1();
        } else {
            CP_WAIT0();
        }
        __syncthreads();
        consume32(sb + (ch & 1) * BUFSZ, acc, wm, wn, lane);
        __syncthreads();
    }

    const float* Bias = prob ? b2g : b2;
    const float* Y    = prob ? G   : P;
    const bool  wb    = (chunk == 0);      // bias rides on chunk 0 (linearity)
    const int qr = lane >> 2, qc = (lane & 3) * 2;
    float local = 0.f;
    #pragma unroll
    for (int mi = 0; mi < 2; ++mi) {
        #pragma unroll
        for (int nj = 0; nj < 4; ++nj) {
            int row = m0 + wm * 32 + mi * 16 + qr;
            int col = n0 + wn * 32 + nj * 8 + qc;
            float bz0 = wb ? Bias[col]     : 0.f;
            float bz1 = wb ? Bias[col + 1] : 0.f;
            float ym0 = ym_s[col - n0], ym1 = ym_s[col - n0 + 1];
            float2 y0 = *reinterpret_cast<const float2*>(&Y[(size_t)row * DIM + col]);
            float2 y1 = *reinterpret_cast<const float2*>(&Y[(size_t)(row + 8) * DIM + col]);
            local += (acc[mi][nj][0] + bz0) * (y0.x - ym0)
                   + (acc[mi][nj][1] + bz1) * (y0.y - ym1)
                   + (acc[mi][nj][2] + bz0) * (y1.x - ym0)
                   + (acc[mi][nj][3] + bz1) * (y1.y - ym1);
        }
    }
    #pragma unroll
    for (int off = 16; off > 0; off >>= 1)
        local += __shfl_xor_sync(0xFFFFFFFF, local, off);
    if (lane == 0) red[wrp] = (double)local;
    __syncthreads();
    if (tid == 0) {
        atomicAdd(&g_acc, (red[0] + red[1]) + (red[2] + red[3]));
        __threadfence();
        unsigned tk = atomicAdd(&g_ticket, 1u);
        if (tk == (unsigned)(gridDim.x - 1)) {       // last block: finish
            double total = atomicAdd(&g_acc, 0.0);   // atomic read (L2-coherent)
            out[0] = (float)(total * (1.0 / NROWS));
        }
    }
}

// ----------------------------------------------------------------------------
extern "C" void kernel_launch(void* const* d_in, const int* in_sizes, int n_in,
                              void* d_out, int out_size)
{
    const float* H   = (const float*)d_in[0];
    const float* P   = (const float*)d_in[1];
    const float* G   = (const float*)d_in[2];
    const float* W1  = (const float*)d_in[3];
    const float* b1  = (const float*)d_in[4];
    const float* W2  = (const float*)d_in[5];
    const float* b2  = (const float*)d_in[6];
    const float* W1g = (const float*)d_in[7];
    const float* b1g = (const float*)d_in[8];
    const float* W2g = (const float*)d_in[9];
    const float* b2g = (const float*)d_in[10];
    float* out = (float*)d_out;

    kPrep<<<640, 256>>>(H, P, G, W1, W1g, W2, W2g);
    kGemm1<<<256, 128>>>(b1, b1g);
    kGemm2<<<256, 128>>>(b2, b2g, P, G, out);
}

// round 11
// speedup vs baseline: 1.1922x; 1.0683x over previous
#include <cuda_runtime.h>
#include <cuda_bf16.h>
#include <cstdint>

#define NROWS 1024
#define DIM   256
#define HID   512
#define RS2   40               // A smem row stride (bf16): 80B, conflict-free
#define ASZ   (64 * RS2 * 2)   // 5120 B : 64m x 32k bf16 tile

// ============================ device scratch =================================
__device__ __align__(16) __nv_bfloat16 g_Xh[2][NROWS * DIM];    // H, P (hi)
__device__ __align__(16) __nv_bfloat16 g_Xl[2][NROWS * DIM];    // H, P (lo)
// weights split elementwise, NATURAL [k][n] layout (n contiguous)
__device__ __align__(16) __nv_bfloat16 g_W1h [DIM * HID],      g_W1l [DIM * HID];
__device__ __align__(16) __nv_bfloat16 g_W1gh[2 * DIM * HID],  g_W1gl[2 * DIM * HID];
__device__ __align__(16) __nv_bfloat16 g_W2h [HID * DIM],      g_W2l [HID * DIM];
__device__ __align__(16) __nv_bfloat16 g_W2gh[HID * DIM],      g_W2gl[HID * DIM];
__device__ __align__(16) __nv_bfloat16 g_A1h[2][NROWS * HID],  g_A1l[2][NROWS * HID];
__device__ __align__(16) float  g_ypart[2 * 32 * DIM];
__device__ double   g_acc;
__device__ unsigned g_ticket;

// ============================ helpers ========================================
__device__ __forceinline__ uint32_t smem_u32(const void* p) {
    uint32_t a;
    asm("{ .reg .u64 t; cvta.to.shared.u64 t, %1; cvt.u32.u64 %0, t; }" : "=r"(a) : "l"(p));
    return a;
}
__device__ __forceinline__ void cvt2(float v0, float v1, uint32_t& hp, uint32_t& lp) {
    __nv_bfloat16 h0 = __float2bfloat16(v0);
    __nv_bfloat16 h1 = __float2bfloat16(v1);
    __nv_bfloat16 l0 = __float2bfloat16(v0 - __bfloat162float(h0));
    __nv_bfloat16 l1 = __float2bfloat16(v1 - __bfloat162float(h1));
    hp = ((uint32_t)__bfloat16_as_ushort(h1) << 16) | __bfloat16_as_ushort(h0);
    lp = ((uint32_t)__bfloat16_as_ushort(l1) << 16) | __bfloat16_as_ushort(l0);
}
__device__ __forceinline__ void mma16816(float* c, const uint32_t* a,
                                         const uint32_t b0, const uint32_t b1) {
    asm volatile(
        "mma.sync.aligned.m16n8k16.row.col.f32.bf16.bf16.f32 "
        "{%0,%1,%2,%3}, {%4,%5,%6,%7}, {%8,%9}, {%0,%1,%2,%3};"
        : "+f"(c[0]), "+f"(c[1]), "+f"(c[2]), "+f"(c[3])
        : "r"(a[0]), "r"(a[1]), "r"(a[2]), "r"(a[3]), "r"(b0), "r"(b1));
}
#define LDSM4(r0, r1, r2, r3, addr)                                              \
    asm volatile("ldmatrix.sync.aligned.m8n8.x4.shared.b16 {%0,%1,%2,%3}, [%4];" \
        : "=r"(r0), "=r"(r1), "=r"(r2), "=r"(r3) : "r"(addr))
#define LDSM4T(r0, r1, r2, r3, addr)                                                   \
    asm volatile("ldmatrix.sync.aligned.m8n8.x4.trans.shared.b16 {%0,%1,%2,%3}, [%4];" \
        : "=r"(r0), "=r"(r1), "=r"(r2), "=r"(r3) : "r"(addr))
#define CP16(dst, src) \
    asm volatile("cp.async.cg.shared.global [%0], [%1], 16;" :: "r"(dst), "l"(src))
#define CP_COMMIT() asm volatile("cp.async.commit_group;" ::: "memory")
#define CP_WAIT1()  asm volatile("cp.async.wait_group 1;" ::: "memory")
#define CP_WAIT0()  asm volatile("cp.async.wait_group 0;" ::: "memory")

// per-NJP tile geometry (NJP = BN/32)
template<int NJP> struct Cfg {
    static constexpr int RSB_ = (NJP == 2) ? 72 : 40;   // B row stride (bf16)
    static constexpr int BSZ_ = 32 * RSB_ * 2;
    static constexpr int OAH = 0, OAL = ASZ, OBH = 2 * ASZ, OBL = 2 * ASZ + BSZ_;
    static constexpr int BUF = 2 * ASZ + 2 * BSZ_;
};

// ============================================================================
// kPrep: streaming splits with 4 units/thread (batched loads, MLP=8) + means.
// grid = 208 x 256. unit = 8 consecutive floats.
// blocks: [0,32) H | [32,64) P | [64,80) W1 | [80,112) W1g | [112,128) W2 |
//         [128,144) W2g | [144,208) means partials
// ============================================================================
__global__ void __launch_bounds__(256) kPrep(const float* __restrict__ H,
                                             const float* __restrict__ P,
                                             const float* __restrict__ G,
                                             const float* __restrict__ W1,
                                             const float* __restrict__ W1g,
                                             const float* __restrict__ W2,
                                             const float* __restrict__ W2g)
{
    const int bid = blockIdx.x, tid = threadIdx.x;
    if (bid == 0 && tid == 0) { g_acc = 0.0; g_ticket = 0u; }

    if (bid < 144) {
        const float* src; __nv_bfloat16 *dh, *dl; int ub;
        if      (bid < 32)  { src = H;   dh = g_Xh[0]; dl = g_Xl[0]; ub = bid * 1024; }
        else if (bid < 64)  { src = P;   dh = g_Xh[1]; dl = g_Xl[1]; ub = (bid - 32) * 1024; }
        else if (bid < 80)  { src = W1;  dh = g_W1h;   dl = g_W1l;   ub = (bid - 64) * 1024; }
        else if (bid < 112) { src = W1g; dh = g_W1gh;  dl = g_W1gl;  ub = (bid - 80) * 1024; }
        else if (bid < 128) { src = W2;  dh = g_W2h;   dl = g_W2l;   ub = (bid - 112) * 1024; }
        else                { src = W2g; dh = g_W2gh;  dl = g_W2gl;  ub = (bid - 128) * 1024; }

        float4 v[8];
        const int base0 = ub * 8;
        #pragma unroll
        for (int j = 0; j < 4; ++j) {          // all loads first -> MLP=8
            int b = base0 + (tid + j * 256) * 8;
            v[2*j]   = *reinterpret_cast<const float4*>(&src[b]);
            v[2*j+1] = *reinterpret_cast<const float4*>(&src[b + 4]);
        }
        #pragma unroll
        for (int j = 0; j < 4; ++j) {
            int b = base0 + (tid + j * 256) * 8;
            uint4 hq, lq;
            cvt2(v[2*j].x,   v[2*j].y,   hq.x, lq.x);
            cvt2(v[2*j].z,   v[2*j].w,   hq.y, lq.y);
            cvt2(v[2*j+1].x, v[2*j+1].y, hq.z, lq.z);
            cvt2(v[2*j+1].z, v[2*j+1].w, hq.w, lq.w);
            *reinterpret_cast<uint4*>(&dh[b]) = hq;
            *reinterpret_cast<uint4*>(&dl[b]) = lq;
        }
        return;
    }

    {                                          // ---- means partials ----
        const int t = bid - 144;
        const int which = t >> 5, part = t & 31;
        const float* Y = which ? G : P;
        const int r0 = part * 32;
        float s = 0.f;
        #pragma unroll 8
        for (int r = 0; r < 32; ++r) s += Y[(r0 + r) * DIM + tid];
        g_ypart[(which * 32 + part) * DIM + tid] = s;
    }
}

// ============================================================================
// cp.async chunk loader: A 64m x 32k ([m][k], lda); B 32k x (32*NJP)n ([k][n], ldb)
// ============================================================================
template<int NJP>
__device__ __forceinline__ void load_async32(uint32_t dst,
    const __nv_bfloat16* __restrict__ Ah, const __nv_bfloat16* __restrict__ Al,
    int m0, int lda, int ka,
    const __nv_bfloat16* __restrict__ Bh, const __nv_bfloat16* __restrict__ Bl,
    int n0, int ldb, int kb, int tid)
{
    using C = Cfg<NJP>;
    #pragma unroll
    for (int i = 0; i < 2; ++i) {
        int idx = tid + i * 128;
        {   // A: 256 granules (64 rows x 4)
            int row = idx >> 2, w = idx & 3;
            uint32_t doff = (uint32_t)row * (RS2 * 2) + w * 16;
            size_t sa = (size_t)(m0 + row) * lda + ka + w * 8;
            CP16(dst + C::OAH + doff, Ah + sa);
            CP16(dst + C::OAL + doff, Al + sa);
        }
        if (NJP == 2 || i == 0) {   // B: 128*NJP granules
            int row, w;
            if (NJP == 2) { row = idx >> 3; w = idx & 7; }
            else          { row = idx >> 2; w = idx & 3; }
            uint32_t doff = (uint32_t)row * (C::RSB_ * 2) + w * 16;
            size_t sbp = (size_t)(kb + row) * ldb + n0 + w * 8;
            CP16(dst + C::OBH + doff, Bh + sbp);
            CP16(dst + C::OBL + doff, Bl + sbp);
        }
    }
}

// ============================================================================
// consume one 64x(32*NJP)x32 chunk: ldmatrix(A) + ldmatrix.trans(B), 3-prod HMMA.
// ============================================================================
template<int NJP>
__device__ __forceinline__ void consume32(uint32_t b, float acc[2][2*NJP][4],
                                          int wm, int wn, int lane)
{
    using C = Cfg<NJP>;
    const int arow  = lane & 15;
    const int akoff = (lane >> 4) * 8;
    const int g     = lane >> 3;
    const int bkrow = (g & 1) * 8 + (lane & 7);
    const int bnoff = (g >> 1) * 8;
    #pragma unroll
    for (int ks = 0; ks < 2; ++ks) {
        const int kb = ks * 16;
        uint32_t ah[2][4], al[2][4];
        #pragma unroll
        for (int mi = 0; mi < 2; ++mi) {
            uint32_t ro = (uint32_t)(wm * 32 + mi * 16 + arow) * (RS2 * 2) + (kb + akoff) * 2;
            LDSM4(ah[mi][0], ah[mi][1], ah[mi][2], ah[mi][3], b + C::OAH + ro);
            LDSM4(al[mi][0], al[mi][1], al[mi][2], al[mi][3], b + C::OAL + ro);
        }
        uint32_t bh[NJP][4], bl[NJP][4];
        #pragma unroll
        for (int njp = 0; njp < NJP; ++njp) {
            uint32_t ro = (uint32_t)(kb + bkrow) * (C::RSB_ * 2)
                        + (wn * 16 * NJP + njp * 16 + bnoff) * 2;
            LDSM4T(bh[njp][0], bh[njp][1], bh[njp][2], bh[njp][3], b + C::OBH + ro);
            LDSM4T(bl[njp][0], bl[njp][1], bl[njp][2], bl[njp][3], b + C::OBL + ro);
        }
        #pragma unroll
        for (int mi = 0; mi < 2; ++mi)
            #pragma unroll
            for (int njp = 0; njp < NJP; ++njp) {
                mma16816(acc[mi][2*njp],     ah[mi], bh[njp][0], bh[njp][1]);
                mma16816(acc[mi][2*njp],     ah[mi], bl[njp][0], bl[njp][1]);
                mma16816(acc[mi][2*njp],     al[mi], bh[njp][0], bh[njp][1]);
                mma16816(acc[mi][2*njp + 1], ah[mi], bh[njp][2], bh[njp][3]);
                mma16816(acc[mi][2*njp + 1], ah[mi], bl[njp][2], bl[njp][3]);
                mma16816(acc[mi][2*njp + 1], al[mi], bh[njp][2], bh[njp][3]);
            }
    }
}

// ============================================================================
// generic double-buffered mainloop. A selected between (Ah0,Al0)/(Ah1,Al1) by
// k0 > kmask (fused concat); ka = k0 & kmask.
// ============================================================================
template<int NJP>
__device__ __forceinline__ void run_main(uint32_t sb, int tid,
    const __nv_bfloat16* Ah0, const __nv_bfloat16* Al0,
    const __nv_bfloat16* Ah1, const __nv_bfloat16* Al1,
    int m0, int lda, int kmask,
    const __nv_bfloat16* Bh, const __nv_bfloat16* Bl, int n0, int ldb,
    int kbeg, int nch, float acc[2][2*NJP][4])
{
    using C = Cfg<NJP>;
    const int lane = tid & 31, wrp = tid >> 5, wm = wrp >> 1, wn = wrp & 1;
    load_async32<NJP>(sb, (kbeg > kmask) ? Ah1 : Ah0, (kbeg > kmask) ? Al1 : Al0,
                      m0, lda, kbeg & kmask, Bh, Bl, n0, ldb, kbeg, tid);
    CP_COMMIT();
    for (int ch = 0; ch < nch; ++ch) {
        if (ch + 1 < nch) {
            int k0 = kbeg + (ch + 1) * 32;
            load_async32<NJP>(sb + ((ch + 1) & 1) * C::BUF,
                              (k0 > kmask) ? Ah1 : Ah0, (k0 > kmask) ? Al1 : Al0,
                              m0, lda, k0 & kmask, Bh, Bl, n0, ldb, k0, tid);
            CP_COMMIT();
            CP_WAIT1();
        } else {
            CP_WAIT0();
        }
        __syncthreads();
        consume32<NJP>(sb + (ch & 1) * C::BUF, acc, wm, wn, lane);
        __syncthreads();
    }
}

template<int NJP>
__device__ __forceinline__ void epilogue1(float acc[2][2*NJP][4], const float* Bias,
    __nv_bfloat16* Oh, __nv_bfloat16* Ol, int m0, int n0, int wm, int wn, int lane)
{
    const int qr = lane >> 2, qc = (lane & 3) * 2;
    #pragma unroll
    for (int mi = 0; mi < 2; ++mi) {
        #pragma unroll
        for (int nj = 0; nj < 2 * NJP; ++nj) {
            int row = m0 + wm * 32 + mi * 16 + qr;
            int col = n0 + wn * 16 * NJP + nj * 8 + qc;
            float bz0 = Bias[col], bz1 = Bias[col + 1];
            uint32_t hp, lp;
            cvt2(fmaxf(acc[mi][nj][0] + bz0, 0.f), fmaxf(acc[mi][nj][1] + bz1, 0.f), hp, lp);
            *reinterpret_cast<uint32_t*>(&Oh[(size_t)row * HID + col]) = hp;
            *reinterpret_cast<uint32_t*>(&Ol[(size_t)row * HID + col]) = lp;
            cvt2(fmaxf(acc[mi][nj][2] + bz0, 0.f), fmaxf(acc[mi][nj][3] + bz1, 0.f), hp, lp);
            *reinterpret_cast<uint32_t*>(&Oh[(size_t)(row + 8) * HID + col]) = hp;
            *reinterpret_cast<uint32_t*>(&Ol[(size_t)(row + 8) * HID + col]) = lp;
        }
    }
}

// ============================================================================
// kGemm1: 384 equal-work CTAs. [0,128): prob0 64x64 tiles (K=256);
// [128,384): prob1 64x32 tiles (K=512, fused concat).
// ============================================================================
__global__ void __launch_bounds__(128) kGemm1(const float* __restrict__ b1,
                                              const float* __restrict__ b1g)
{
    __shared__ __align__(16) char bufs[2 * Cfg<2>::BUF];
    const uint32_t sb = smem_u32(bufs);
    const int tid  = threadIdx.x;
    const int lane = tid & 31, wrp = tid >> 5;
    const int wm   = wrp >> 1, wn = wrp & 1;
    const int bid  = blockIdx.x;

    if (bid < 128) {
        const int m0 = (bid >> 3) * 64, n0 = (bid & 7) * 64;
        float acc[2][4][4] = {};
        run_main<2>(sb, tid, g_Xh[0], g_Xl[0], g_Xh[0], g_Xl[0],
                    m0, DIM, 255, g_W1h, g_W1l, n0, HID, 0, 8, acc);
        epilogue1<2>(acc, b1, g_A1h[0], g_A1l[0], m0, n0, wm, wn, lane);
    } else {
        const int t = bid - 128;
        const int m0 = (t >> 4) * 64, n0 = (t & 15) * 32;
        float acc[2][2][4] = {};
        run_main<1>(sb, tid, g_Xh[0], g_Xl[0], g_Xh[1], g_Xl[1],
                    m0, DIM, 255, g_W1gh, g_W1gl, n0, HID, 0, 16, acc);
        epilogue1<1>(acc, b1g, g_A1h[1], g_A1l[1], m0, n0, wm, wn, lane);
    }
}

// ============================================================================
// kGemm2: split-K x4, fused CLUB epilogue, ticket-fused finish.
// 512 CTAs: prob(2) x m(16) x n(4) x chunk(4); K=128 per chunk.
// ============================================================================
__global__ void __launch_bounds__(128) kGemm2(const float* __restrict__ b2,
                                              const float* __restrict__ b2g,
                                              const float* __restrict__ P,
                                              const float* __restrict__ G,
                                              float* __restrict__ out)
{
    __shared__ __align__(16) char bufs[2 * Cfg<2>::BUF];
    __shared__ float  ym_s[64];
    __shared__ double red[4];
    const uint32_t sb = smem_u32(bufs);
    const int tid  = threadIdx.x;
    const int lane = tid & 31, wrp = tid >> 5;
    const int wm   = wrp >> 1, wn = wrp & 1;
    const int bid  = blockIdx.x;
    const int prob  = bid >> 8, t = bid & 255;
    const int m0    = (t >> 4) * 64;
    const int n0    = ((t >> 2) & 3) * 64;
    const int chunk = t & 3;
    const int kbeg  = chunk * 128;

    if (tid < 64) {                        // ym for this n-tile
        float sm = 0.f;
        #pragma unroll 8
        for (int b = 0; b < 32; ++b) sm += g_ypart[(prob * 32 + b) * DIM + n0 + tid];
        ym_s[tid] = sm * (1.0f / NROWS);
    }

    const __nv_bfloat16* Ah = g_A1h[prob];
    const __nv_bfloat16* Al = g_A1l[prob];
    const __nv_bfloat16* Wh = prob ? g_W2gh : g_W2h;
    const __nv_bfloat16* Wl = prob ? g_W2gl : g_W2l;

    float acc[2][4][4] = {};
    run_main<2>(sb, tid, Ah, Al, Ah, Al, m0, HID, 0x0FFFFFFF,
                Wh, Wl, n0, DIM, kbeg, 4, acc);

    const float* Bias = prob ? b2g : b2;
    const float* Y    = prob ? G   : P;
    const bool  wb    = (chunk == 0);      // bias rides on chunk 0 (linearity)
    const int qr = lane >> 2, qc = (lane & 3) * 2;
    float local = 0.f;
    #pragma unroll
    for (int mi = 0; mi < 2; ++mi) {
        #pragma unroll
        for (int nj = 0; nj < 4; ++nj) {
            int row = m0 + wm * 32 + mi * 16 + qr;
            int col = n0 + wn * 32 + nj * 8 + qc;
            float bz0 = wb ? Bias[col]     : 0.f;
            float bz1 = wb ? Bias[col + 1] : 0.f;
            float ym0 = ym_s[col - n0], ym1 = ym_s[col - n0 + 1];
            float2 y0 = *reinterpret_cast<const float2*>(&Y[(size_t)row * DIM + col]);
            float2 y1 = *reinterpret_cast<const float2*>(&Y[(size_t)(row + 8) * DIM + col]);
            local += (acc[mi][nj][0] + bz0) * (y0.x - ym0)
                   + (acc[mi][nj][1] + bz1) * (y0.y - ym1)
                   + (acc[mi][nj][2] + bz0) * (y1.x - ym0)
                   + (acc[mi][nj][3] + bz1) * (y1.y - ym1);
        }
    }
    #pragma unroll
    for (int off = 16; off > 0; off >>= 1)
        local += __shfl_xor_sync(0xFFFFFFFF, local, off);
    if (lane == 0) red[wrp] = (double)local;
    __syncthreads();
    if (tid == 0) {
        atomicAdd(&g_acc, (red[0] + red[1]) + (red[2] + red[3]));
        __threadfence();
        unsigned tk = atomicAdd(&g_ticket, 1u);
        if (tk == (unsigned)(gridDim.x - 1)) {       // last block: finish
            double total = atomicAdd(&g_acc, 0.0);   // atomic read (L2-coherent)
            out[0] = (float)(total * (1.0 / NROWS));
        }
    }
}

// ----------------------------------------------------------------------------
extern "C" void kernel_launch(void* const* d_in, const int* in_sizes, int n_in,
                              void* d_out, int out_size)
{
    const float* H   = (const float*)d_in[0];
    const float* P   = (const float*)d_in[1];
    const float* G   = (const float*)d_in[2];
    const float* W1  = (const float*)d_in[3];
    const float* b1  = (const float*)d_in[4];
    const float* W2  = (const float*)d_in[5];
    const float* b2  = (const float*)d_in[6];
    const float* W1g = (const float*)d_in[7];
    const float* b1g = (const float*)d_in[8];
    const float* W2g = (const float*)d_in[9];
    const float* b2g = (const float*)d_in[10];
    float* out = (float*)d_out;

    kPrep<<<208, 256>>>(H, P, G, W1, W1g, W2, W2g);
    kGemm1<<<384, 128>>>(b1, b1g);
    kGemm2<<<512, 128>>>(b2, b2g, P, G, out);
}